// round 4
// baseline (speedup 1.0000x reference)
#include <cuda_runtime.h>
#include <cuda_bf16.h>

// ScalableHashGrid: InstantNGP-style multires hash grid encoding.
// 2^20 points x 10 levels x 4 feature dims, trilinear interp of 8 corners.
// Levels 0-2 dense (res 16/32/64), levels 3-9 hashed into 2^21-entry tables.
//
// Layout: 2 threads per point (lane parity = x-corner side). The hash prime
// for x is 1, so the two x-corners of a cell are table entries h and h^1
// whenever ix is even -> adjacent lanes of the same warp LDG hit the same
// 32B sector and L1tex merges them (the binder is L1tex wavefronts, not DRAM).
// Each thread-pair walks all 10 levels (x read once), pair-reduces via shfl,
// stages results in smem, and the block writes its output contiguously.

namespace {
constexpr int N_POINTS   = 1 << 20;
constexpr int NUM_LEVELS = 10;
constexpr unsigned HASH_MASK = (1u << 21) - 1u;
constexpr unsigned PRIME_Y = 2654435761u;
constexpr unsigned PRIME_Z = 805459861u;

// Per-level resolution and float4 offset into the concatenated table.
// SIZES = ceil8(min((r+1)^3, 2^21)): 4920, 35944, 274632, then 7 x 2097152.
__device__ constexpr int RES[NUM_LEVELS] = {16, 32, 64, 128, 256, 512, 1024, 2048, 4096, 8192};
__device__ constexpr int OFF[NUM_LEVELS] = {0, 4920, 40864, 315496, 2412648,
                                            4509800, 6606952, 8704104, 10801256, 12898408};

constexpr int THREADS      = 256;
constexpr int PTS_PER_BLK  = THREADS / 2;         // 128 points per block
constexpr int STAGE_STRIDE = NUM_LEVELS + 1;      // pad to 11 float4 vs bank patterns
}

__global__ __launch_bounds__(THREADS)
void hashgrid_kernel(const float* __restrict__ x,
                     const float4* __restrict__ table,
                     float4* __restrict__ out)
{
    __shared__ float4 stage[PTS_PER_BLK * STAGE_STRIDE];

    const int tid = threadIdx.x;
    const int t   = blockIdx.x * THREADS + tid;
    const int n   = t >> 1;                 // point index
    const unsigned s = (unsigned)(t & 1);   // x-corner side (0 or 1)
    const int p_local = tid >> 1;

    // Lane s=0 loads the point; broadcast to its pair lane via shfl.
    float x0 = 0.f, x1 = 0.f, x2 = 0.f;
    if (s == 0) {
        x0 = x[3 * n + 0];
        x1 = x[3 * n + 1];
        x2 = x[3 * n + 2];
    }
    const int src = tid & ~1;  // even lane of the pair (within warp: lane & ~1)
    x0 = (__shfl_sync(0xffffffffu, x0, src & 31) + 1.0f) * 0.5f;
    x1 = (__shfl_sync(0xffffffffu, x1, src & 31) + 1.0f) * 0.5f;
    x2 = (__shfl_sync(0xffffffffu, x2, src & 31) + 1.0f) * 0.5f;

#pragma unroll
    for (int l = 0; l < NUM_LEVELS; ++l) {
        const int   res   = RES[l];
        const float scale = (float)res - 1.0f;

        const float posx = x0 * scale + 0.5f;
        const float posy = x1 * scale + 0.5f;
        const float posz = x2 * scale + 0.5f;

        const float flx = floorf(posx);
        const float fly = floorf(posy);
        const float flz = floorf(posz);
        const float fx = posx - flx;
        const float fy = posy - fly;
        const float fz = posz - flz;

        const unsigned ix = (unsigned)flx;
        const unsigned iy = (unsigned)fly;
        const unsigned iz = (unsigned)flz;

        const unsigned xc = ix + s;                  // this lane's x corner
        const float    wx = s ? fx : (1.0f - fx);    // this lane's x weight

        // 4 (y,z) corners for this x side: (y,z) = (0,0),(1,0),(0,1),(1,1)
        unsigned i00, i10, i01, i11;
        if (l < 3) {
            // Dense: idx = x + y*(res+1) + z*(res+1)^2
            const unsigned r1 = (unsigned)(res + 1);
            const unsigned y0 = iy * r1,      y1 = y0 + r1;
            const unsigned z0 = iz * r1 * r1, z1 = z0 + r1 * r1;
            i00 = xc + y0 + z0;
            i10 = xc + y1 + z0;
            i01 = xc + y0 + z1;
            i11 = xc + y1 + z1;
        } else {
            // Hashed: (x*1 ^ y*P1 ^ z*P2) & (2^21-1)
            const unsigned hy0 = iy * PRIME_Y, hy1 = hy0 + PRIME_Y;
            const unsigned hz0 = iz * PRIME_Z, hz1 = hz0 + PRIME_Z;
            i00 = (xc ^ hy0 ^ hz0) & HASH_MASK;
            i10 = (xc ^ hy1 ^ hz0) & HASH_MASK;
            i01 = (xc ^ hy0 ^ hz1) & HASH_MASK;
            i11 = (xc ^ hy1 ^ hz1) & HASH_MASK;
        }

        // Issue all 4 gathers before any use (MLP=4 per lane, 8 per point).
        const float4* __restrict__ tab = table + OFF[l];
        const float4 e00 = __ldg(tab + i00);
        const float4 e10 = __ldg(tab + i10);
        const float4 e01 = __ldg(tab + i01);
        const float4 e11 = __ldg(tab + i11);

        const float w00 = wx * (1.0f - fy) * (1.0f - fz);
        const float w10 = wx * fy          * (1.0f - fz);
        const float w01 = wx * (1.0f - fy) * fz;
        const float w11 = wx * fy          * fz;

        float4 acc;
        acc.x = w00 * e00.x + w10 * e10.x + w01 * e01.x + w11 * e11.x;
        acc.y = w00 * e00.y + w10 * e10.y + w01 * e01.y + w11 * e11.y;
        acc.z = w00 * e00.z + w10 * e10.z + w01 * e01.z + w11 * e11.z;
        acc.w = w00 * e00.w + w10 * e10.w + w01 * e01.w + w11 * e11.w;

        // Sum the two x-sides across the lane pair.
        acc.x += __shfl_xor_sync(0xffffffffu, acc.x, 1);
        acc.y += __shfl_xor_sync(0xffffffffu, acc.y, 1);
        acc.z += __shfl_xor_sync(0xffffffffu, acc.z, 1);
        acc.w += __shfl_xor_sync(0xffffffffu, acc.w, 1);

        if (s == 0) {
            stage[p_local * STAGE_STRIDE + l] = acc;
        }
    }

    __syncthreads();

    // Coalesced write: this block's 128 points x 10 float4 = 1280 float4,
    // contiguous in gmem starting at block * 1280 (out[n*10 + l]).
    const int out_base = blockIdx.x * (PTS_PER_BLK * NUM_LEVELS);
#pragma unroll
    for (int i = 0; i < (PTS_PER_BLK * NUM_LEVELS) / THREADS; ++i) {
        const int j  = tid + i * THREADS;     // 0..1279
        const int p  = j / NUM_LEVELS;
        const int lv = j - p * NUM_LEVELS;
        out[out_base + j] = stage[p * STAGE_STRIDE + lv];
    }
}

extern "C" void kernel_launch(void* const* d_in, const int* in_sizes, int n_in,
                              void* d_out, int out_size)
{
    const float*  x     = (const float*)d_in[0];
    const float4* table = (const float4*)d_in[1];
    float4*       out   = (float4*)d_out;

    const int blocks = (N_POINTS * 2) / THREADS;   // 8192, exact
    hashgrid_kernel<<<blocks, THREADS>>>(x, table, out);
}

// round 6
// speedup vs baseline: 1.8144x; 1.8144x over previous
#include <cuda_runtime.h>
#include <cuda_bf16.h>

// ScalableHashGrid: InstantNGP-style multires hash grid encoding.
// 2^20 points x 10 levels x 4 feature dims, trilinear interp of 8 corners.
// Levels 0-2 dense (res 16/32/64), levels 3-9 hashed into 2^21-entry tables.
//
// R5 design:
//  * 5 level-PAIR passes (templated launches): concurrent working set is two
//    tables (<=64MB) -> resident in 126MB L2, so each hashed 32B sector is
//    fetched from DRAM once (~32MB/level) and re-hit in L2 (~8x reuse).
//  * 2 threads per point (lane parity = x-corner side). x hash prime is 1, so
//    the cell's two x-corners live in one 32B sector when ix is even ->
//    adjacent lanes merge in L1tex (fewer wavefronts + fewer L2 sectors).
//  * Each thread-pair emits BOTH levels of the pair for its point: the two
//    float4 outputs exactly fill one aligned 32B sector -> no partial-sector
//    write amplification.

namespace {
constexpr int N_POINTS   = 1 << 20;
constexpr int NUM_LEVELS = 10;
constexpr unsigned HASH_MASK = (1u << 21) - 1u;
constexpr unsigned PRIME_Y = 2654435761u;
constexpr unsigned PRIME_Z = 805459861u;

// Per-level resolution and float4 offset into the concatenated table.
// SIZES = ceil8(min((r+1)^3, 2^21)): 4920, 35944, 274632, then 7 x 2097152.
constexpr int RES[NUM_LEVELS] = {16, 32, 64, 128, 256, 512, 1024, 2048, 4096, 8192};
constexpr int OFF[NUM_LEVELS] = {0, 4920, 40864, 315496, 2412648,
                                 4509800, 6606952, 8704104, 10801256, 12898408};

constexpr int THREADS = 256;
constexpr int BLOCKS  = (N_POINTS * 2) / THREADS;   // 8192 per pass
}

// Compute the 4 (y,z) corner gather indices for this thread's x-side at a
// compile-time level, plus issue the gathers. Returns the weighted sum of the
// 4 corners (this lane's half of the trilinear interpolation).
template <int L>
__device__ __forceinline__ float4 level_half(
    const float4* __restrict__ table,
    float x0, float x1, float x2, unsigned s)
{
    constexpr int   res   = RES[L];
    constexpr float scale = (float)res - 1.0f;

    const float posx = x0 * scale + 0.5f;
    const float posy = x1 * scale + 0.5f;
    const float posz = x2 * scale + 0.5f;

    const float flx = floorf(posx);
    const float fly = floorf(posy);
    const float flz = floorf(posz);
    const float fx = posx - flx;
    const float fy = posy - fly;
    const float fz = posz - flz;

    const unsigned ix = (unsigned)flx;
    const unsigned iy = (unsigned)fly;
    const unsigned iz = (unsigned)flz;

    const unsigned xc = ix + s;                  // this lane's x corner
    const float    wx = s ? fx : (1.0f - fx);    // this lane's x weight

    unsigned i00, i10, i01, i11;                 // (y,z) = (0,0),(1,0),(0,1),(1,1)
    if constexpr (L < 3) {
        // Dense: idx = x + y*(res+1) + z*(res+1)^2
        constexpr unsigned r1 = (unsigned)(res + 1);
        const unsigned y0 = iy * r1,      y1 = y0 + r1;
        const unsigned z0 = iz * r1 * r1, z1 = z0 + r1 * r1;
        i00 = xc + y0 + z0;
        i10 = xc + y1 + z0;
        i01 = xc + y0 + z1;
        i11 = xc + y1 + z1;
    } else {
        // Hashed: (x*1 ^ y*P1 ^ z*P2) & (2^21-1)
        const unsigned hy0 = iy * PRIME_Y, hy1 = hy0 + PRIME_Y;
        const unsigned hz0 = iz * PRIME_Z, hz1 = hz0 + PRIME_Z;
        i00 = (xc ^ hy0 ^ hz0) & HASH_MASK;
        i10 = (xc ^ hy1 ^ hz0) & HASH_MASK;
        i01 = (xc ^ hy0 ^ hz1) & HASH_MASK;
        i11 = (xc ^ hy1 ^ hz1) & HASH_MASK;
    }

    const float4* __restrict__ tab = table + OFF[L];
    const float4 e00 = __ldg(tab + i00);
    const float4 e10 = __ldg(tab + i10);
    const float4 e01 = __ldg(tab + i01);
    const float4 e11 = __ldg(tab + i11);

    const float w00 = wx * (1.0f - fy) * (1.0f - fz);
    const float w10 = wx * fy          * (1.0f - fz);
    const float w01 = wx * (1.0f - fy) * fz;
    const float w11 = wx * fy          * fz;

    float4 acc;
    acc.x = w00 * e00.x + w10 * e10.x + w01 * e01.x + w11 * e11.x;
    acc.y = w00 * e00.y + w10 * e10.y + w01 * e01.y + w11 * e11.y;
    acc.z = w00 * e00.z + w10 * e10.z + w01 * e01.z + w11 * e11.z;
    acc.w = w00 * e00.w + w10 * e10.w + w01 * e01.w + w11 * e11.w;
    return acc;
}

template <int LEVEL0>
__global__ __launch_bounds__(THREADS)
void hashgrid_pair_kernel(const float* __restrict__ x,
                          const float4* __restrict__ table,
                          float4* __restrict__ out)
{
    const int tid = threadIdx.x;
    const int t   = blockIdx.x * THREADS + tid;
    const int n   = t >> 1;                 // point index
    const unsigned s = (unsigned)(t & 1);   // x-corner side (0 or 1)

    // Both pair lanes load the same point: same-address lanes are merged /
    // broadcast by L1tex, so this costs the same sectors as a lone load.
    const float x0 = (__ldg(&x[3 * n + 0]) + 1.0f) * 0.5f;
    const float x1 = (__ldg(&x[3 * n + 1]) + 1.0f) * 0.5f;
    const float x2 = (__ldg(&x[3 * n + 2]) + 1.0f) * 0.5f;

    float4 a0 = level_half<LEVEL0>(table, x0, x1, x2, s);
    float4 a1 = level_half<LEVEL0 + 1>(table, x0, x1, x2, s);

    // Sum the two x-sides across the lane pair.
    a0.x += __shfl_xor_sync(0xffffffffu, a0.x, 1);
    a0.y += __shfl_xor_sync(0xffffffffu, a0.y, 1);
    a0.z += __shfl_xor_sync(0xffffffffu, a0.z, 1);
    a0.w += __shfl_xor_sync(0xffffffffu, a0.w, 1);
    a1.x += __shfl_xor_sync(0xffffffffu, a1.x, 1);
    a1.y += __shfl_xor_sync(0xffffffffu, a1.y, 1);
    a1.z += __shfl_xor_sync(0xffffffffu, a1.z, 1);
    a1.w += __shfl_xor_sync(0xffffffffu, a1.w, 1);

    if (s == 0) {
        // out[n*10 + LEVEL0] and +1: one full, aligned 32B sector.
        float4* o = out + (n * NUM_LEVELS + LEVEL0);
        o[0] = a0;
        o[1] = a1;
    }
}

extern "C" void kernel_launch(void* const* d_in, const int* in_sizes, int n_in,
                              void* d_out, int out_size)
{
    const float*  x     = (const float*)d_in[0];
    const float4* table = (const float4*)d_in[1];
    float4*       out   = (float4*)d_out;

    hashgrid_pair_kernel<0><<<BLOCKS, THREADS>>>(x, table, out);
    hashgrid_pair_kernel<2><<<BLOCKS, THREADS>>>(x, table, out);
    hashgrid_pair_kernel<4><<<BLOCKS, THREADS>>>(x, table, out);
    hashgrid_pair_kernel<6><<<BLOCKS, THREADS>>>(x, table, out);
    hashgrid_pair_kernel<8><<<BLOCKS, THREADS>>>(x, table, out);
}

// round 7
// speedup vs baseline: 1.9566x; 1.0784x over previous
#include <cuda_runtime.h>
#include <cuda_bf16.h>

// ScalableHashGrid: InstantNGP-style multires hash grid encoding.
// 2^20 points x 10 levels x 4 feature dims, trilinear interp of 8 corners.
// Levels 0-2 dense (res 16/32/64), levels 3-9 hashed into 2^21-entry tables.
//
// R6 design (on top of the R5 win):
//  * 4 passes: {0,1,2,3} (dense tables tiny + one 32MB hashed = 37MB hot),
//    then hashed pairs {4,5},{6,7},{8,9} (64MB hot each) -> L2-resident.
//  * 2 threads per point (lane parity = x-corner side); x hash prime is 1 so
//    the cell's two x-corners share a 32B sector when ix is even -> adjacent
//    lanes merge in L1tex/L2.
//  * Streaming traffic (x reads, output stores) uses evict-first hints
//    (__ldcs/__stcs) so it doesn't evict hot table sectors from L2 --
//    R5's measured 238MB/pass vs ~108MB compulsory was table re-fetch.
//  * Paired 32B-aligned float4 stores: no partial-sector write amplification.

namespace {
constexpr int N_POINTS   = 1 << 20;
constexpr int NUM_LEVELS = 10;
constexpr unsigned HASH_MASK = (1u << 21) - 1u;
constexpr unsigned PRIME_Y = 2654435761u;
constexpr unsigned PRIME_Z = 805459861u;

// Per-level resolution and float4 offset into the concatenated table.
// SIZES = ceil8(min((r+1)^3, 2^21)): 4920, 35944, 274632, then 7 x 2097152.
constexpr int RES[NUM_LEVELS] = {16, 32, 64, 128, 256, 512, 1024, 2048, 4096, 8192};
constexpr int OFF[NUM_LEVELS] = {0, 4920, 40864, 315496, 2412648,
                                 4509800, 6606952, 8704104, 10801256, 12898408};

constexpr int THREADS = 256;
constexpr int BLOCKS  = (N_POINTS * 2) / THREADS;   // 8192 per pass
}

// This lane's half (4 of 8 corners) of the trilinear interp at level L.
template <int L>
__device__ __forceinline__ float4 level_half(
    const float4* __restrict__ table,
    float x0, float x1, float x2, unsigned s)
{
    constexpr int   res   = RES[L];
    constexpr float scale = (float)res - 1.0f;

    const float posx = x0 * scale + 0.5f;
    const float posy = x1 * scale + 0.5f;
    const float posz = x2 * scale + 0.5f;

    const float flx = floorf(posx);
    const float fly = floorf(posy);
    const float flz = floorf(posz);
    const float fx = posx - flx;
    const float fy = posy - fly;
    const float fz = posz - flz;

    const unsigned ix = (unsigned)flx;
    const unsigned iy = (unsigned)fly;
    const unsigned iz = (unsigned)flz;

    const unsigned xc = ix + s;                  // this lane's x corner
    const float    wx = s ? fx : (1.0f - fx);    // this lane's x weight

    unsigned i00, i10, i01, i11;                 // (y,z) = (0,0),(1,0),(0,1),(1,1)
    if constexpr (L < 3) {
        // Dense: idx = x + y*(res+1) + z*(res+1)^2
        constexpr unsigned r1 = (unsigned)(res + 1);
        const unsigned y0 = iy * r1,      y1 = y0 + r1;
        const unsigned z0 = iz * r1 * r1, z1 = z0 + r1 * r1;
        i00 = xc + y0 + z0;
        i10 = xc + y1 + z0;
        i01 = xc + y0 + z1;
        i11 = xc + y1 + z1;
    } else {
        // Hashed: (x*1 ^ y*P1 ^ z*P2) & (2^21-1)
        const unsigned hy0 = iy * PRIME_Y, hy1 = hy0 + PRIME_Y;
        const unsigned hz0 = iz * PRIME_Z, hz1 = hz0 + PRIME_Z;
        i00 = (xc ^ hy0 ^ hz0) & HASH_MASK;
        i10 = (xc ^ hy1 ^ hz0) & HASH_MASK;
        i01 = (xc ^ hy0 ^ hz1) & HASH_MASK;
        i11 = (xc ^ hy1 ^ hz1) & HASH_MASK;
    }

    const float4* __restrict__ tab = table + OFF[L];
    const float4 e00 = __ldg(tab + i00);
    const float4 e10 = __ldg(tab + i10);
    const float4 e01 = __ldg(tab + i01);
    const float4 e11 = __ldg(tab + i11);

    const float w00 = wx * (1.0f - fy) * (1.0f - fz);
    const float w10 = wx * fy          * (1.0f - fz);
    const float w01 = wx * (1.0f - fy) * fz;
    const float w11 = wx * fy          * fz;

    float4 acc;
    acc.x = w00 * e00.x + w10 * e10.x + w01 * e01.x + w11 * e11.x;
    acc.y = w00 * e00.y + w10 * e10.y + w01 * e01.y + w11 * e11.y;
    acc.z = w00 * e00.z + w10 * e10.z + w01 * e01.z + w11 * e11.z;
    acc.w = w00 * e00.w + w10 * e10.w + w01 * e01.w + w11 * e11.w;
    return acc;
}

// Compute levels L0 and L0+1 for this point, pair-reduce, store 32B (s==0).
template <int L0>
__device__ __forceinline__ void do_pair(
    const float4* __restrict__ table, float4* __restrict__ out,
    float x0, float x1, float x2, unsigned s, int n)
{
    float4 a0 = level_half<L0>(table, x0, x1, x2, s);
    float4 a1 = level_half<L0 + 1>(table, x0, x1, x2, s);

    a0.x += __shfl_xor_sync(0xffffffffu, a0.x, 1);
    a0.y += __shfl_xor_sync(0xffffffffu, a0.y, 1);
    a0.z += __shfl_xor_sync(0xffffffffu, a0.z, 1);
    a0.w += __shfl_xor_sync(0xffffffffu, a0.w, 1);
    a1.x += __shfl_xor_sync(0xffffffffu, a1.x, 1);
    a1.y += __shfl_xor_sync(0xffffffffu, a1.y, 1);
    a1.z += __shfl_xor_sync(0xffffffffu, a1.z, 1);
    a1.w += __shfl_xor_sync(0xffffffffu, a1.w, 1);

    if (s == 0) {
        float4* o = out + (n * NUM_LEVELS + L0);
        __stcs(o + 0, a0);   // streaming store: evict-first, keep tables hot
        __stcs(o + 1, a1);
    }
}

__device__ __forceinline__ void load_point(
    const float* __restrict__ x, int n, float& x0, float& x1, float& x2)
{
    // Streaming reads (evict-first): x is touched once per pass.
    x0 = (__ldcs(&x[3 * n + 0]) + 1.0f) * 0.5f;
    x1 = (__ldcs(&x[3 * n + 1]) + 1.0f) * 0.5f;
    x2 = (__ldcs(&x[3 * n + 2]) + 1.0f) * 0.5f;
}

// Pass A: levels 0..3 (dense 0-2 + hashed 3). Two sequential pair blocks keep
// register pressure at the R5 level while amortizing the x read over 4 levels.
__global__ __launch_bounds__(THREADS)
void hashgrid_quad_kernel(const float* __restrict__ x,
                          const float4* __restrict__ table,
                          float4* __restrict__ out)
{
    const int t = blockIdx.x * THREADS + threadIdx.x;
    const int n = t >> 1;
    const unsigned s = (unsigned)(t & 1);

    float x0, x1, x2;
    load_point(x, n, x0, x1, x2);

    do_pair<0>(table, out, x0, x1, x2, s, n);
    do_pair<2>(table, out, x0, x1, x2, s, n);
}

template <int L0>
__global__ __launch_bounds__(THREADS)
void hashgrid_pair_kernel(const float* __restrict__ x,
                          const float4* __restrict__ table,
                          float4* __restrict__ out)
{
    const int t = blockIdx.x * THREADS + threadIdx.x;
    const int n = t >> 1;
    const unsigned s = (unsigned)(t & 1);

    float x0, x1, x2;
    load_point(x, n, x0, x1, x2);

    do_pair<L0>(table, out, x0, x1, x2, s, n);
}

extern "C" void kernel_launch(void* const* d_in, const int* in_sizes, int n_in,
                              void* d_out, int out_size)
{
    const float*  x     = (const float*)d_in[0];
    const float4* table = (const float4*)d_in[1];
    float4*       out   = (float4*)d_out;

    hashgrid_quad_kernel   <<<BLOCKS, THREADS>>>(x, table, out);
    hashgrid_pair_kernel<4><<<BLOCKS, THREADS>>>(x, table, out);
    hashgrid_pair_kernel<6><<<BLOCKS, THREADS>>>(x, table, out);
    hashgrid_pair_kernel<8><<<BLOCKS, THREADS>>>(x, table, out);
}

// round 13
// speedup vs baseline: 1.9586x; 1.0010x over previous
#include <cuda_runtime.h>
#include <cuda_bf16.h>

// ScalableHashGrid: InstantNGP-style multires hash grid encoding.
// 2^20 points x 10 levels x 4 feature dims, trilinear interp of 8 corners.
// Levels 0-2 dense (res 16/32/64), levels 3-9 hashed into 2^21-entry tables.
//
// R12 design (R6 + table pinning via cache-hint policy register):
//  * 4 passes: {0,1,2,3} then hashed pairs {4,5},{6,7},{8,9}; hot table set
//    per pass <= 64MB, resident in the ~126MB L2.
//  * Table gathers: createpolicy.fractional.L2::evict_last.b64 pol, 1.0;
//    then ld.global.nc.L2::cache_hint.v4.f32 (the direct .L2::evict_last
//    qualifier is illegal on sub-256-bit loads per ptxas; the policy-register
//    form is width-agnostic). Pins hot table sectors at lowest eviction
//    priority: R6 measured 231MB DRAM/pass vs ~108MB compulsory = table
//    re-fetch under evict-normal.
//  * Streaming traffic (x reads __ldcs, out stores __stcs) is evict-first.
//  * 2 threads per point (lane parity = x-corner side); x hash prime is 1 so
//    the cell's two x-corners share a 32B sector when ix is even -> adjacent
//    lanes merge in L1tex/L2.
//  * Each thread-pair emits both levels of its pair: the two float4 stores
//    fill one aligned 32B sector (no partial-sector write amplification).

namespace {
constexpr int N_POINTS   = 1 << 20;
constexpr int NUM_LEVELS = 10;
constexpr unsigned HASH_MASK = (1u << 21) - 1u;
constexpr unsigned PRIME_Y = 2654435761u;
constexpr unsigned PRIME_Z = 805459861u;

// Per-level resolution and float4 offset into the concatenated table.
// SIZES = ceil8(min((r+1)^3, 2^21)): 4920, 35944, 274632, then 7 x 2097152.
constexpr int RES[NUM_LEVELS] = {16, 32, 64, 128, 256, 512, 1024, 2048, 4096, 8192};
constexpr int OFF[NUM_LEVELS] = {0, 4920, 40864, 315496, 2412648,
                                 4509800, 6606952, 8704104, 10801256, 12898408};

constexpr int THREADS = 256;
constexpr int BLOCKS  = (N_POINTS * 2) / THREADS;   // 8192 per pass
}

// L2 evict_last policy, fraction 1.0 (canonical PTX ISA form).
__device__ __forceinline__ unsigned long long make_evict_last_policy()
{
    unsigned long long p;
    asm("createpolicy.fractional.L2::evict_last.b64 %0, 1.0;" : "=l"(p));
    return p;
}

// Read-only table gather with L2 evict_last cache hint.
__device__ __forceinline__ float4 ldg_table(const float4* p, unsigned long long pol)
{
    float4 v;
    asm("ld.global.nc.L2::cache_hint.v4.f32 {%0,%1,%2,%3}, [%4], %5;"
        : "=f"(v.x), "=f"(v.y), "=f"(v.z), "=f"(v.w)
        : "l"(p), "l"(pol));
    return v;
}

// This lane's half (4 of 8 corners) of the trilinear interp at level L.
template <int L>
__device__ __forceinline__ float4 level_half(
    const float4* __restrict__ table,
    float x0, float x1, float x2, unsigned s, unsigned long long pol)
{
    constexpr int   res   = RES[L];
    constexpr float scale = (float)res - 1.0f;

    const float posx = x0 * scale + 0.5f;
    const float posy = x1 * scale + 0.5f;
    const float posz = x2 * scale + 0.5f;

    const float flx = floorf(posx);
    const float fly = floorf(posy);
    const float flz = floorf(posz);
    const float fx = posx - flx;
    const float fy = posy - fly;
    const float fz = posz - flz;

    const unsigned ix = (unsigned)flx;
    const unsigned iy = (unsigned)fly;
    const unsigned iz = (unsigned)flz;

    const unsigned xc = ix + s;                  // this lane's x corner
    const float    wx = s ? fx : (1.0f - fx);    // this lane's x weight

    unsigned i00, i10, i01, i11;                 // (y,z) = (0,0),(1,0),(0,1),(1,1)
    if constexpr (L < 3) {
        // Dense: idx = x + y*(res+1) + z*(res+1)^2
        constexpr unsigned r1 = (unsigned)(res + 1);
        const unsigned y0 = iy * r1,      y1 = y0 + r1;
        const unsigned z0 = iz * r1 * r1, z1 = z0 + r1 * r1;
        i00 = xc + y0 + z0;
        i10 = xc + y1 + z0;
        i01 = xc + y0 + z1;
        i11 = xc + y1 + z1;
    } else {
        // Hashed: (x*1 ^ y*P1 ^ z*P2) & (2^21-1)
        const unsigned hy0 = iy * PRIME_Y, hy1 = hy0 + PRIME_Y;
        const unsigned hz0 = iz * PRIME_Z, hz1 = hz0 + PRIME_Z;
        i00 = (xc ^ hy0 ^ hz0) & HASH_MASK;
        i10 = (xc ^ hy1 ^ hz0) & HASH_MASK;
        i01 = (xc ^ hy0 ^ hz1) & HASH_MASK;
        i11 = (xc ^ hy1 ^ hz1) & HASH_MASK;
    }

    const float4* __restrict__ tab = table + OFF[L];
    const float4 e00 = ldg_table(tab + i00, pol);
    const float4 e10 = ldg_table(tab + i10, pol);
    const float4 e01 = ldg_table(tab + i01, pol);
    const float4 e11 = ldg_table(tab + i11, pol);

    const float w00 = wx * (1.0f - fy) * (1.0f - fz);
    const float w10 = wx * fy          * (1.0f - fz);
    const float w01 = wx * (1.0f - fy) * fz;
    const float w11 = wx * fy          * fz;

    float4 acc;
    acc.x = w00 * e00.x + w10 * e10.x + w01 * e01.x + w11 * e11.x;
    acc.y = w00 * e00.y + w10 * e10.y + w01 * e01.y + w11 * e11.y;
    acc.z = w00 * e00.z + w10 * e10.z + w01 * e01.z + w11 * e11.z;
    acc.w = w00 * e00.w + w10 * e10.w + w01 * e01.w + w11 * e11.w;
    return acc;
}

// Compute levels L0 and L0+1 for this point, pair-reduce, store 32B (s==0).
template <int L0>
__device__ __forceinline__ void do_pair(
    const float4* __restrict__ table, float4* __restrict__ out,
    float x0, float x1, float x2, unsigned s, int n, unsigned long long pol)
{
    float4 a0 = level_half<L0>(table, x0, x1, x2, s, pol);
    float4 a1 = level_half<L0 + 1>(table, x0, x1, x2, s, pol);

    a0.x += __shfl_xor_sync(0xffffffffu, a0.x, 1);
    a0.y += __shfl_xor_sync(0xffffffffu, a0.y, 1);
    a0.z += __shfl_xor_sync(0xffffffffu, a0.z, 1);
    a0.w += __shfl_xor_sync(0xffffffffu, a0.w, 1);
    a1.x += __shfl_xor_sync(0xffffffffu, a1.x, 1);
    a1.y += __shfl_xor_sync(0xffffffffu, a1.y, 1);
    a1.z += __shfl_xor_sync(0xffffffffu, a1.z, 1);
    a1.w += __shfl_xor_sync(0xffffffffu, a1.w, 1);

    if (s == 0) {
        float4* o = out + (n * NUM_LEVELS + L0);
        __stcs(o + 0, a0);   // streaming store: evict-first, keep tables hot
        __stcs(o + 1, a1);
    }
}

__device__ __forceinline__ void load_point(
    const float* __restrict__ x, int n, float& x0, float& x1, float& x2)
{
    // Streaming reads (evict-first): x is touched once per pass.
    x0 = (__ldcs(&x[3 * n + 0]) + 1.0f) * 0.5f;
    x1 = (__ldcs(&x[3 * n + 1]) + 1.0f) * 0.5f;
    x2 = (__ldcs(&x[3 * n + 2]) + 1.0f) * 0.5f;
}

// Pass A: levels 0..3 (dense 0-2 + hashed 3).
__global__ __launch_bounds__(THREADS)
void hashgrid_quad_kernel(const float* __restrict__ x,
                          const float4* __restrict__ table,
                          float4* __restrict__ out)
{
    const int t = blockIdx.x * THREADS + threadIdx.x;
    const int n = t >> 1;
    const unsigned s = (unsigned)(t & 1);
    const unsigned long long pol = make_evict_last_policy();

    float x0, x1, x2;
    load_point(x, n, x0, x1, x2);

    do_pair<0>(table, out, x0, x1, x2, s, n, pol);
    do_pair<2>(table, out, x0, x1, x2, s, n, pol);
}

template <int L0>
__global__ __launch_bounds__(THREADS)
void hashgrid_pair_kernel(const float* __restrict__ x,
                          const float4* __restrict__ table,
                          float4* __restrict__ out)
{
    const int t = blockIdx.x * THREADS + threadIdx.x;
    const int n = t >> 1;
    const unsigned s = (unsigned)(t & 1);
    const unsigned long long pol = make_evict_last_policy();

    float x0, x1, x2;
    load_point(x, n, x0, x1, x2);

    do_pair<L0>(table, out, x0, x1, x2, s, n, pol);
}

extern "C" void kernel_launch(void* const* d_in, const int* in_sizes, int n_in,
                              void* d_out, int out_size)
{
    const float*  x     = (const float*)d_in[0];
    const float4* table = (const float4*)d_in[1];
    float4*       out   = (float4*)d_out;

    hashgrid_quad_kernel   <<<BLOCKS, THREADS>>>(x, table, out);
    hashgrid_pair_kernel<4><<<BLOCKS, THREADS>>>(x, table, out);
    hashgrid_pair_kernel<6><<<BLOCKS, THREADS>>>(x, table, out);
    hashgrid_pair_kernel<8><<<BLOCKS, THREADS>>>(x, table, out);
}